// round 4
// baseline (speedup 1.0000x reference)
#include <cuda_runtime.h>
#include <cuda_bf16.h>

// out = relu(x @ W^T + b)
// x: [M=32768, 256] fp32 (row-major, K-contiguous)
// W: [256, 256] fp32 (row-major, K-contiguous)  -> NT GEMM
// b: [256]
//
// Key insight: reference's softmax attention sums to 1 over axis j, so
// einsum('nkj,nkd->nkd', a, h) == h exactly (up to fp rounding).
// Final answer is relu(h) = relu(x @ W^T + b).

#define BM 128
#define BN 128
#define BK 16
#define TM 8
#define TN 8

__global__ __launch_bounds__(256, 2)
void fcgat_gemm_relu(const float* __restrict__ X,
                     const float* __restrict__ W,
                     const float* __restrict__ bias,
                     float* __restrict__ out,
                     int M, int Kdim, int Ndim) {
    __shared__ float As[BK][BM];      // As[k][m]
    __shared__ float Bs[BK][BN];      // Bs[k][e] = W[e][k]

    const int tid = threadIdx.x;          // 0..255
    const int bm = blockIdx.x * BM;
    const int bn = blockIdx.y * BN;

    const int tx = tid & 15;              // 0..15 -> column group (e)
    const int ty = tid >> 4;              // 0..15 -> row group (m)

    float acc[TM][TN];
    #pragma unroll
    for (int i = 0; i < TM; i++)
        #pragma unroll
        for (int j = 0; j < TN; j++)
            acc[i][j] = 0.0f;

    for (int k0 = 0; k0 < Kdim; k0 += BK) {
        // ---- load A tile: 128 rows x 16 k = 512 float4, 2 per thread ----
        #pragma unroll
        for (int f = tid; f < (BM * BK) / 4; f += 256) {
            int row = f >> 2;              // 0..127
            int c4  = (f & 3) << 2;        // 0,4,8,12
            float4 v = *(const float4*)(X + (size_t)(bm + row) * Kdim + k0 + c4);
            As[c4 + 0][row] = v.x;
            As[c4 + 1][row] = v.y;
            As[c4 + 2][row] = v.z;
            As[c4 + 3][row] = v.w;
        }
        // ---- load B tile (W transposed on the fly) ----
        #pragma unroll
        for (int f = tid; f < (BN * BK) / 4; f += 256) {
            int e  = f >> 2;               // 0..127
            int c4 = (f & 3) << 2;
            float4 v = *(const float4*)(W + (size_t)(bn + e) * Kdim + k0 + c4);
            Bs[c4 + 0][e] = v.x;
            Bs[c4 + 1][e] = v.y;
            Bs[c4 + 2][e] = v.z;
            Bs[c4 + 3][e] = v.w;
        }
        __syncthreads();

        // ---- 8x8 outer-product micro-kernel ----
        #pragma unroll
        for (int kk = 0; kk < BK; kk++) {
            float a[TM], b[TN];
            // vectorized LDS.128 reads
            float4 a0 = *(const float4*)&As[kk][ty * TM + 0];
            float4 a1 = *(const float4*)&As[kk][ty * TM + 4];
            float4 b0 = *(const float4*)&Bs[kk][tx * TN + 0];
            float4 b1 = *(const float4*)&Bs[kk][tx * TN + 4];
            a[0]=a0.x; a[1]=a0.y; a[2]=a0.z; a[3]=a0.w;
            a[4]=a1.x; a[5]=a1.y; a[6]=a1.z; a[7]=a1.w;
            b[0]=b0.x; b[1]=b0.y; b[2]=b0.z; b[3]=b0.w;
            b[4]=b1.x; b[5]=b1.y; b[6]=b1.z; b[7]=b1.w;
            #pragma unroll
            for (int i = 0; i < TM; i++)
                #pragma unroll
                for (int j = 0; j < TN; j++)
                    acc[i][j] = fmaf(a[i], b[j], acc[i][j]);
        }
        __syncthreads();
    }

    // ---- epilogue: bias + relu, float4 stores ----
    #pragma unroll
    for (int i = 0; i < TM; i++) {
        int row = bm + ty * TM + i;
        #pragma unroll
        for (int j = 0; j < TN; j += 4) {
            int col = bn + tx * TN + j;
            float4 r;
            r.x = fmaxf(acc[i][j + 0] + bias[col + 0], 0.0f);
            r.y = fmaxf(acc[i][j + 1] + bias[col + 1], 0.0f);
            r.z = fmaxf(acc[i][j + 2] + bias[col + 2], 0.0f);
            r.w = fmaxf(acc[i][j + 3] + bias[col + 3], 0.0f);
            *(float4*)(out + (size_t)row * Ndim + col) = r;
        }
    }
}

extern "C" void kernel_launch(void* const* d_in, const int* in_sizes, int n_in,
                              void* d_out, int out_size) {
    const float* x    = (const float*)d_in[0];   // [64,512,256]
    const float* W_w  = (const float*)d_in[1];   // [256,256]
    const float* W_b  = (const float*)d_in[2];   // [256]
    // d_in[3] = att_w, d_in[4] = att_b : mathematically irrelevant (softmax sums to 1)
    float* out = (float*)d_out;                  // [64,512,256]

    const int M = 64 * 512;   // 32768
    const int K = 256;
    const int N = 256;

    dim3 grid(M / BM, N / BN);   // (256, 2)
    dim3 block(256);
    fcgat_gemm_relu<<<grid, block>>>(x, W_w, W_b, out, M, K, N);
}

// round 10
// speedup vs baseline: 1.8916x; 1.8916x over previous
#include <cuda_runtime.h>
#include <cuda_bf16.h>
#include <stdint.h>

// out = relu(x @ W^T + b)  [softmax attention weights sum to 1 => attention = identity]
// Base-arch (compute_103, NO 'a' features) tensor-core path:
//   mma.sync.m16n8k16 bf16 + ldmatrix + cp.async  (all sm_80/75 base features)
// 3-way bf16 split for fp32-like accuracy: D = Xh*Wh + Xh*Wl + Xl*Wh.

#define MDIM 32768
#define KDIM 256
#define NDIM 256

// -------- device scratch (static globals; no allocation) --------
__device__ __nv_bfloat16 g_Xh[MDIM * KDIM];
__device__ __nv_bfloat16 g_Xl[MDIM * KDIM];
__device__ __nv_bfloat16 g_Wh[NDIM * KDIM];
__device__ __nv_bfloat16 g_Wl[NDIM * KDIM];

// -------- helpers --------
__device__ __forceinline__ uint32_t smem_u32(const void* p) {
    uint32_t a;
    asm("{ .reg .u64 t; cvta.to.shared.u64 t, %1; cvt.u32.u64 %0, t; }" : "=r"(a) : "l"(p));
    return a;
}
// pack: lower half = bf16(f0), upper half = bf16(f1)  (memory order f0,f1)
__device__ __forceinline__ uint32_t pack2(float f0, float f1) {
    uint32_t r;
    asm("cvt.rn.bf16x2.f32 %0, %1, %2;" : "=r"(r) : "f"(f1), "f"(f0));
    return r;
}
__device__ __forceinline__ float u2f(uint32_t u) { return __uint_as_float(u); }

__device__ __forceinline__ void cp16(uint32_t dst, const void* src) {
    asm volatile("cp.async.cg.shared.global [%0], [%1], 16;" :: "r"(dst), "l"(src));
}
__device__ __forceinline__ void cp_commit() {
    asm volatile("cp.async.commit_group;" ::: "memory");
}
template <int N> __device__ __forceinline__ void cp_wait() {
    asm volatile("cp.async.wait_group %0;" :: "n"(N) : "memory");
}
__device__ __forceinline__ void ldm_x4(uint32_t* r, uint32_t addr) {
    asm volatile("ldmatrix.sync.aligned.m8n8.x4.shared.b16 {%0,%1,%2,%3}, [%4];"
                 : "=r"(r[0]), "=r"(r[1]), "=r"(r[2]), "=r"(r[3]) : "r"(addr));
}
__device__ __forceinline__ void mma16816(float* d, const uint32_t* a, const uint32_t* b) {
    asm volatile("mma.sync.aligned.m16n8k16.row.col.f32.bf16.bf16.f32 "
                 "{%0,%1,%2,%3}, {%4,%5,%6,%7}, {%8,%9}, {%0,%1,%2,%3};"
                 : "+f"(d[0]), "+f"(d[1]), "+f"(d[2]), "+f"(d[3])
                 : "r"(a[0]), "r"(a[1]), "r"(a[2]), "r"(a[3]), "r"(b[0]), "r"(b[1]));
}

// -------- kernel 1: split fp32 -> (hi, lo) bf16 --------
__global__ __launch_bounds__(256)
void split_kernel(const float* __restrict__ X, const float* __restrict__ W) {
    const int NX4 = MDIM * KDIM / 4;   // 2097152
    const int NW4 = NDIM * KDIM / 4;   // 16384
    int idx = blockIdx.x * 256 + threadIdx.x;
    const float4* src;
    uint2 *dh, *dl;
    int j;
    if (idx < NX4) {
        src = (const float4*)X; j = idx;
        dh = (uint2*)g_Xh; dl = (uint2*)g_Xl;
    } else if (idx < NX4 + NW4) {
        src = (const float4*)W; j = idx - NX4;
        dh = (uint2*)g_Wh; dl = (uint2*)g_Wl;
    } else return;

    float4 v = src[j];
    uint32_t h01 = pack2(v.x, v.y);
    uint32_t h23 = pack2(v.z, v.w);
    float r0 = v.x - u2f(h01 << 16);
    float r1 = v.y - u2f(h01 & 0xFFFF0000u);
    float r2 = v.z - u2f(h23 << 16);
    float r3 = v.w - u2f(h23 & 0xFFFF0000u);
    dh[j] = make_uint2(h01, h23);
    dl[j] = make_uint2(pack2(r0, r1), pack2(r2, r3));
}

// -------- kernel 2: bf16 split-3 GEMM + bias + relu --------
// CTA tile 128x128, BK=32, 3-stage cp.async pipeline.
// smem stage = AH(8K) AL(8K) BH(8K) BL(8K) = 32KB; rows = 64B (32 bf16, 4x16B chunks),
// chunk swizzle: phys_c = c ^ (row & 3).
#define BK 32
#define STAGES 3
#define STAGE_BYTES 32768
#define AH_O 0
#define AL_O 8192
#define BH_O 16384
#define BL_O 24576
#define KITERS (KDIM / BK)   // 8

__device__ __forceinline__ void issue_stage(uint32_t sb, int it, int m0, int n0, int tid) {
    uint32_t base = sb + (uint32_t)(it % STAGES) * STAGE_BYTES;
    int kbase = it * BK;
#pragma unroll
    for (int h = 0; h < 2; h++) {
        int f = tid + h * 256;          // 0..511 chunk id per tile
        int row = f >> 2;
        int c = f & 3;
        uint32_t sw = (uint32_t)row * 64 + ((uint32_t)(c ^ (row & 3)) << 4);
        size_t aoff = (size_t)(m0 + row) * KDIM + kbase + c * 8;
        size_t boff = (size_t)(n0 + row) * KDIM + kbase + c * 8;
        cp16(base + AH_O + sw, g_Xh + aoff);
        cp16(base + AL_O + sw, g_Xl + aoff);
        cp16(base + BH_O + sw, g_Wh + boff);
        cp16(base + BL_O + sw, g_Wl + boff);
    }
}

__global__ __launch_bounds__(256, 1)
void gemm_bf16split(const float* __restrict__ bias, float* __restrict__ out) {
    extern __shared__ char smem[];
    const uint32_t sb = smem_u32(smem);
    const int tid = threadIdx.x;
    const int lane = tid & 31;
    const int wid = tid >> 5;
    const int wm = wid & 3;          // warp m index (32 rows each)
    const int wn = wid >> 2;         // warp n index (64 cols each)
    const int m0 = blockIdx.x * 128;
    const int n0 = blockIdx.y * 128;

    const int g = lane >> 2;         // mma group id (row within 8)
    const int tig = lane & 3;        // thread in group
    const int asub = lane >> 3;      // ldmatrix sub-matrix id 0..3

    // ldmatrix address roles
    const int a_row_base = wm * 32 + (asub & 1) * 8 + (lane & 7); // + mt*16
    const int a_cadd = asub >> 1;                                  // + ks*2
    const int b_row_base = wn * 64 + (asub >> 1) * 8 + (lane & 7); // + ntp*16
    const int b_cadd = asub & 1;                                   // + ks*2

    float acc[2][8][4];
#pragma unroll
    for (int i = 0; i < 2; i++)
#pragma unroll
        for (int j = 0; j < 8; j++)
#pragma unroll
            for (int q = 0; q < 4; q++) acc[i][j][q] = 0.0f;

    // bias registers (cols owned by this thread)
    float bs[8][2];
#pragma unroll
    for (int nt = 0; nt < 8; nt++) {
        int col = n0 + wn * 64 + nt * 8 + 2 * tig;
        float2 b2 = *(const float2*)(bias + col);
        bs[nt][0] = b2.x; bs[nt][1] = b2.y;
    }

    issue_stage(sb, 0, m0, n0, tid); cp_commit();
    issue_stage(sb, 1, m0, n0, tid); cp_commit();

    for (int it = 0; it < KITERS; it++) {
        if (it + 2 < KITERS) issue_stage(sb, it + 2, m0, n0, tid);
        cp_commit();
        cp_wait<2>();
        __syncthreads();

        uint32_t base = sb + (uint32_t)(it % STAGES) * STAGE_BYTES;

#pragma unroll
        for (int ks = 0; ks < 2; ks++) {
            uint32_t aH[2][4], aL[2][4], bH[4][4], bL[4][4];
#pragma unroll
            for (int mt = 0; mt < 2; mt++) {
                int row = a_row_base + mt * 16;
                int c = ks * 2 + a_cadd;
                uint32_t sw = (uint32_t)row * 64 + ((uint32_t)(c ^ (row & 3)) << 4);
                ldm_x4(aH[mt], base + AH_O + sw);
                ldm_x4(aL[mt], base + AL_O + sw);
            }
#pragma unroll
            for (int ntp = 0; ntp < 4; ntp++) {
                int row = b_row_base + ntp * 16;
                int c = ks * 2 + b_cadd;
                uint32_t sw = (uint32_t)row * 64 + ((uint32_t)(c ^ (row & 3)) << 4);
                ldm_x4(bH[ntp], base + BH_O + sw);
                ldm_x4(bL[ntp], base + BL_O + sw);
            }
#pragma unroll
            for (int mt = 0; mt < 2; mt++)
#pragma unroll
                for (int ntp = 0; ntp < 4; ntp++)
#pragma unroll
                    for (int hf = 0; hf < 2; hf++) {
                        float* d = acc[mt][ntp * 2 + hf];
                        mma16816(d, aH[mt], &bH[ntp][hf * 2]);   // Xh*Wh
                        mma16816(d, aH[mt], &bL[ntp][hf * 2]);   // Xh*Wl
                        mma16816(d, aL[mt], &bH[ntp][hf * 2]);   // Xl*Wh
                    }
        }
        __syncthreads();
    }

    // epilogue: bias + relu, float2 stores
#pragma unroll
    for (int mt = 0; mt < 2; mt++) {
        int row = m0 + wm * 32 + mt * 16 + g;
#pragma unroll
        for (int nt = 0; nt < 8; nt++) {
            int col = n0 + wn * 64 + nt * 8 + 2 * tig;
            const float* d = acc[mt][nt];
            float2 o0, o1;
            o0.x = fmaxf(d[0] + bs[nt][0], 0.0f);
            o0.y = fmaxf(d[1] + bs[nt][1], 0.0f);
            o1.x = fmaxf(d[2] + bs[nt][0], 0.0f);
            o1.y = fmaxf(d[3] + bs[nt][1], 0.0f);
            *(float2*)(out + (size_t)row * NDIM + col) = o0;
            *(float2*)(out + (size_t)(row + 8) * NDIM + col) = o1;
        }
    }
}

extern "C" void kernel_launch(void* const* d_in, const int* in_sizes, int n_in,
                              void* d_out, int out_size) {
    const float* x    = (const float*)d_in[0];   // [64,512,256]
    const float* W_w  = (const float*)d_in[1];   // [256,256]
    const float* W_b  = (const float*)d_in[2];   // [256]
    float* out = (float*)d_out;                  // [64,512,256]

    // split X and W into hi/lo bf16
    const int NX4 = MDIM * KDIM / 4, NW4 = NDIM * KDIM / 4;
    int nblk = (NX4 + NW4 + 255) / 256;          // 8256
    split_kernel<<<nblk, 256>>>(x, W_w);

    static bool configured = false;
    if (!configured) {
        cudaFuncSetAttribute(gemm_bf16split,
                             cudaFuncAttributeMaxDynamicSharedMemorySize,
                             STAGES * STAGE_BYTES);
        configured = true;
    }
    dim3 grid(MDIM / 128, NDIM / 128);           // (256, 2)
    gemm_bf16split<<<grid, 256, STAGES * STAGE_BYTES>>>(W_b, out);
}

// round 13
// speedup vs baseline: 2.0854x; 1.1025x over previous
#include <cuda_runtime.h>
#include <cuda_bf16.h>
#include <stdint.h>

// out = relu(x @ W^T + b)  [softmax attention weights sum to 1 => attention = identity]
// Base-arch (compute_103) tensor-core path: mma.sync.m16n8k16 bf16 + ldmatrix + cp.async.
// 3-way bf16 split for fp32-like accuracy: D = Xh*Wh + Xh*Wl + Xl*Wh.
//
// R10 -> R11: regs 152 -> <=128 via __launch_bounds__(256,2) (bias moved to smem)
// so 2 CTAs/SM co-reside: occ 12.5% -> 25%, waves 3.46 -> 1.73.

#define MDIM 32768
#define KDIM 256
#define NDIM 256

// -------- device scratch (static globals; no allocation) --------
__device__ __nv_bfloat16 g_Xh[MDIM * KDIM];
__device__ __nv_bfloat16 g_Xl[MDIM * KDIM];
__device__ __nv_bfloat16 g_Wh[NDIM * KDIM];
__device__ __nv_bfloat16 g_Wl[NDIM * KDIM];

// -------- helpers --------
__device__ __forceinline__ uint32_t smem_u32(const void* p) {
    uint32_t a;
    asm("{ .reg .u64 t; cvta.to.shared.u64 t, %1; cvt.u32.u64 %0, t; }" : "=r"(a) : "l"(p));
    return a;
}
// pack: lower half = bf16(f0), upper half = bf16(f1)  (memory order f0,f1)
__device__ __forceinline__ uint32_t pack2(float f0, float f1) {
    uint32_t r;
    asm("cvt.rn.bf16x2.f32 %0, %1, %2;" : "=r"(r) : "f"(f1), "f"(f0));
    return r;
}
__device__ __forceinline__ float u2f(uint32_t u) { return __uint_as_float(u); }

__device__ __forceinline__ void cp16(uint32_t dst, const void* src) {
    asm volatile("cp.async.cg.shared.global [%0], [%1], 16;" :: "r"(dst), "l"(src));
}
__device__ __forceinline__ void cp_commit() {
    asm volatile("cp.async.commit_group;" ::: "memory");
}
template <int N> __device__ __forceinline__ void cp_wait() {
    asm volatile("cp.async.wait_group %0;" :: "n"(N) : "memory");
}
__device__ __forceinline__ void ldm_x4(uint32_t* r, uint32_t addr) {
    asm volatile("ldmatrix.sync.aligned.m8n8.x4.shared.b16 {%0,%1,%2,%3}, [%4];"
                 : "=r"(r[0]), "=r"(r[1]), "=r"(r[2]), "=r"(r[3]) : "r"(addr));
}
__device__ __forceinline__ void mma16816(float* d, const uint32_t* a, const uint32_t* b) {
    asm volatile("mma.sync.aligned.m16n8k16.row.col.f32.bf16.bf16.f32 "
                 "{%0,%1,%2,%3}, {%4,%5,%6,%7}, {%8,%9}, {%0,%1,%2,%3};"
                 : "+f"(d[0]), "+f"(d[1]), "+f"(d[2]), "+f"(d[3])
                 : "r"(a[0]), "r"(a[1]), "r"(a[2]), "r"(a[3]), "r"(b[0]), "r"(b[1]));
}

// -------- kernel 1: split fp32 -> (hi, lo) bf16 --------
__global__ __launch_bounds__(256)
void split_kernel(const float* __restrict__ X, const float* __restrict__ W) {
    const int NX4 = MDIM * KDIM / 4;   // 2097152
    const int NW4 = NDIM * KDIM / 4;   // 16384
    int idx = blockIdx.x * 256 + threadIdx.x;
    const float4* src;
    uint2 *dh, *dl;
    int j;
    if (idx < NX4) {
        src = (const float4*)X; j = idx;
        dh = (uint2*)g_Xh; dl = (uint2*)g_Xl;
    } else if (idx < NX4 + NW4) {
        src = (const float4*)W; j = idx - NX4;
        dh = (uint2*)g_Wh; dl = (uint2*)g_Wl;
    } else return;

    float4 v = src[j];
    uint32_t h01 = pack2(v.x, v.y);
    uint32_t h23 = pack2(v.z, v.w);
    float r0 = v.x - u2f(h01 << 16);
    float r1 = v.y - u2f(h01 & 0xFFFF0000u);
    float r2 = v.z - u2f(h23 << 16);
    float r3 = v.w - u2f(h23 & 0xFFFF0000u);
    dh[j] = make_uint2(h01, h23);
    dl[j] = make_uint2(pack2(r0, r1), pack2(r2, r3));
}

// -------- kernel 2: bf16 split-3 GEMM + bias + relu --------
// CTA tile 128x128, BK=32, 3-stage cp.async pipeline, 2 CTAs/SM.
// smem = [bias 1KB][stage0 32KB][stage1][stage2]; stage = AH AL BH BL (8KB each);
// rows = 64B (32 bf16, 4x16B chunks), chunk swizzle: phys_c = c ^ (row & 3).
#define BK 32
#define STAGES 3
#define STAGE_BYTES 32768
#define BIAS_BYTES 1024
#define AH_O 0
#define AL_O 8192
#define BH_O 16384
#define BL_O 24576
#define KITERS (KDIM / BK)   // 8
#define SMEM_TOTAL (BIAS_BYTES + STAGES * STAGE_BYTES)   // 99328... (1024 + 98304)

__device__ __forceinline__ void issue_stage(uint32_t stages_base, int it, int m0, int n0, int tid) {
    uint32_t base = stages_base + (uint32_t)(it % STAGES) * STAGE_BYTES;
    int kbase = it * BK;
#pragma unroll
    for (int h = 0; h < 2; h++) {
        int f = tid + h * 256;          // 0..511 chunk id per tile
        int row = f >> 2;
        int c = f & 3;
        uint32_t sw = (uint32_t)row * 64 + ((uint32_t)(c ^ (row & 3)) << 4);
        size_t aoff = (size_t)(m0 + row) * KDIM + kbase + c * 8;
        size_t boff = (size_t)(n0 + row) * KDIM + kbase + c * 8;
        cp16(base + AH_O + sw, g_Xh + aoff);
        cp16(base + AL_O + sw, g_Xl + aoff);
        cp16(base + BH_O + sw, g_Wh + boff);
        cp16(base + BL_O + sw, g_Wl + boff);
    }
}

__global__ __launch_bounds__(256, 2)
void gemm_bf16split(const float* __restrict__ bias, float* __restrict__ out) {
    extern __shared__ char smem[];
    const uint32_t sb = smem_u32(smem);
    const uint32_t stages_base = sb + BIAS_BYTES;
    const int tid = threadIdx.x;
    const int lane = tid & 31;
    const int wid = tid >> 5;
    const int wm = wid & 3;          // warp m index (32 rows each)
    const int wn = wid >> 2;         // warp n index (64 cols each)
    const int m0 = blockIdx.x * 128;
    const int n0 = blockIdx.y * 128;

    const int g = lane >> 2;         // mma group id (row within 8)
    const int tig = lane & 3;        // thread in group
    const int asub = lane >> 3;      // ldmatrix sub-matrix id 0..3

    // bias -> smem (CTA's 128-col slab: cols [n0, n0+128) stored at [0,128))
    if (tid < 128) ((float*)smem)[tid] = bias[n0 + tid];

    // ldmatrix address roles
    const int a_row_base = wm * 32 + (asub & 1) * 8 + (lane & 7); // + mt*16
    const int a_cadd = asub >> 1;                                  // + ks*2
    const int b_row_base = wn * 64 + (asub >> 1) * 8 + (lane & 7); // + ntp*16
    const int b_cadd = asub & 1;                                   // + ks*2

    float acc[2][8][4];
#pragma unroll
    for (int i = 0; i < 2; i++)
#pragma unroll
        for (int j = 0; j < 8; j++)
#pragma unroll
            for (int q = 0; q < 4; q++) acc[i][j][q] = 0.0f;

    issue_stage(stages_base, 0, m0, n0, tid); cp_commit();
    issue_stage(stages_base, 1, m0, n0, tid); cp_commit();

    for (int it = 0; it < KITERS; it++) {
        if (it + 2 < KITERS) issue_stage(stages_base, it + 2, m0, n0, tid);
        cp_commit();
        cp_wait<2>();
        __syncthreads();

        uint32_t base = stages_base + (uint32_t)(it % STAGES) * STAGE_BYTES;

#pragma unroll
        for (int ks = 0; ks < 2; ks++) {
            uint32_t aH[2][4], aL[2][4], bH[4][4], bL[4][4];
#pragma unroll
            for (int mt = 0; mt < 2; mt++) {
                int row = a_row_base + mt * 16;
                int c = ks * 2 + a_cadd;
                uint32_t sw = (uint32_t)row * 64 + ((uint32_t)(c ^ (row & 3)) << 4);
                ldm_x4(aH[mt], base + AH_O + sw);
                ldm_x4(aL[mt], base + AL_O + sw);
            }
#pragma unroll
            for (int ntp = 0; ntp < 4; ntp++) {
                int row = b_row_base + ntp * 16;
                int c = ks * 2 + b_cadd;
                uint32_t sw = (uint32_t)row * 64 + ((uint32_t)(c ^ (row & 3)) << 4);
                ldm_x4(bH[ntp], base + BH_O + sw);
                ldm_x4(bL[ntp], base + BL_O + sw);
            }
#pragma unroll
            for (int mt = 0; mt < 2; mt++)
#pragma unroll
                for (int ntp = 0; ntp < 4; ntp++)
#pragma unroll
                    for (int hf = 0; hf < 2; hf++) {
                        float* d = acc[mt][ntp * 2 + hf];
                        mma16816(d, aH[mt], &bH[ntp][hf * 2]);   // Xh*Wh
                        mma16816(d, aH[mt], &bL[ntp][hf * 2]);   // Xh*Wl
                        mma16816(d, aL[mt], &bH[ntp][hf * 2]);   // Xl*Wh
                    }
        }
        __syncthreads();
    }

    // epilogue: bias (from smem) + relu, float2 stores
    const float* sbias = (const float*)smem;
#pragma unroll
    for (int mt = 0; mt < 2; mt++) {
        int row = m0 + wm * 32 + mt * 16 + g;
#pragma unroll
        for (int nt = 0; nt < 8; nt++) {
            int lcol = wn * 64 + nt * 8 + 2 * tig;       // 0..127 within CTA slab
            int col = n0 + lcol;
            float b0 = sbias[lcol], b1 = sbias[lcol + 1];
            const float* d = acc[mt][nt];
            float2 o0, o1;
            o0.x = fmaxf(d[0] + b0, 0.0f);
            o0.y = fmaxf(d[1] + b1, 0.0f);
            o1.x = fmaxf(d[2] + b0, 0.0f);
            o1.y = fmaxf(d[3] + b1, 0.0f);
            *(float2*)(out + (size_t)row * NDIM + col) = o0;
            *(float2*)(out + (size_t)(row + 8) * NDIM + col) = o1;
        }
    }
}

extern "C" void kernel_launch(void* const* d_in, const int* in_sizes, int n_in,
                              void* d_out, int out_size) {
    const float* x    = (const float*)d_in[0];   // [64,512,256]
    const float* W_w  = (const float*)d_in[1];   // [256,256]
    const float* W_b  = (const float*)d_in[2];   // [256]
    float* out = (float*)d_out;                  // [64,512,256]

    // split X and W into hi/lo bf16
    const int NX4 = MDIM * KDIM / 4, NW4 = NDIM * KDIM / 4;
    int nblk = (NX4 + NW4 + 255) / 256;          // 8256
    split_kernel<<<nblk, 256>>>(x, W_w);

    static bool configured = false;
    if (!configured) {
        cudaFuncSetAttribute(gemm_bf16split,
                             cudaFuncAttributeMaxDynamicSharedMemorySize,
                             SMEM_TOTAL);
        configured = true;
    }
    dim3 grid(MDIM / 128, NDIM / 128);           // (256, 2)
    gemm_bf16split<<<grid, 256, SMEM_TOTAL>>>(W_b, out);
}